// round 1
// baseline (speedup 1.0000x reference)
#include <cuda_runtime.h>
#include <math.h>

#define T_DATA 100000
#define K_DIM  1000
#define SUB    20
#define TSYN   201

// ---------------- scratch (device globals: no allocs allowed) ----------------
__device__ float g_syn[2][SUB][T_DATA];   // [e/i][s][t] column(T)-contig, 16 MB

typedef unsigned long long u64;

__device__ __forceinline__ u64 fma2(u64 a, u64 b, u64 c){
    u64 d; asm("fma.rn.f32x2 %0, %1, %2, %3;" : "=l"(d) : "l"(a), "l"(b), "l"(c)); return d;
}
__device__ __forceinline__ u64 pack2(float x, float y){
    u64 d; asm("mov.b64 %0, {%1, %2};" : "=l"(d) : "f"(x), "f"(y)); return d;
}
__device__ __forceinline__ float2 unpack2(u64 a){
    float2 r; asm("mov.b64 {%0, %1}, %2;" : "=f"(r.x), "=f"(r.y) : "l"(a)); return r;
}

// ============================ GEMM kernel ====================================
// syn_e[t,s] = sum_k S_e[t,k] * C_e[s,k]   (and same for i)
// TM=256 rows/CTA. 256 threads: warp w handles output cols n0=w*5 (0..39,
// <20 -> e, >=20 -> i), lane m handles row-pairs {64p+2m, 64p+2m+1}, p=0..3.
// Accumulators are f32x2 over the row pair (fma.rn.f32x2 => 2x fp32 rate).
#define TM     256
#define KC     20
#define NKC    50        // 1000 / 20
#define SPITCH 258       // 256 rows + 2 pad (bank spread, keeps 8B align)

__global__ __launch_bounds__(256, 2) void gemm_kernel(
    const float* __restrict__ Se, const float* __restrict__ Si,
    const float* __restrict__ Ce, const float* __restrict__ Ci)
{
    extern __shared__ float sm[];
    float* Ssm = sm;                      // [2 buf][2 mat][KC][SPITCH]  (transposed: [k][row])
    float* Csm = sm + 2*2*KC*SPITCH;      // [2 buf][40][KC]  (linear idx == cidx since KC==20)

    const int tid  = threadIdx.x;
    const int warp = tid >> 5;
    const int m    = tid & 31;
    const int row0 = blockIdx.x * TM;
    const int mymat = (warp >= 4) ? 1 : 0;
    const int n0   = warp * 5;            // 0..35
    const int sloc = (warp & 3) * 5;      // sub index within my matrix

    u64 acc[4][5];
    #pragma unroll
    for (int p = 0; p < 4; p++)
        #pragma unroll
        for (int j = 0; j < 5; j++) acc[p][j] = 0ULL;

    // staging pointers: fidx = tid + i*256 -> row = fidx/5, col = fidx%5 (col = float4 index)
    const float* pA[5];
    const long dBA = (long)(Si - Se);
    #pragma unroll
    for (int i = 0; i < 5; i++){
        int fidx = tid + i*256;
        int row = fidx / 5, col = fidx % 5;
        int gr = row0 + row; if (gr >= T_DATA) gr = T_DATA - 1;   // clamp (stores guarded)
        pA[i] = Se + (size_t)gr * K_DIM + 4*col;
    }
    // C staging: cidx = tid + i*256 < 800 ; n = cidx/20, k = cidx%20
    const float* pC[4];
    #pragma unroll
    for (int i = 0; i < 4; i++){
        int cidx = tid + i*256;
        int c2 = (cidx < 800) ? cidx : 0;
        int nn = c2 / 20, kk = c2 % 20;
        pC[i] = ((nn < 20) ? Ce : Ci) + (size_t)((nn < 20) ? nn : nn - 20) * K_DIM + kk;
    }

    float4 stA[5], stB[5];
    float  stC[4];

    // stage chunk 0
    #pragma unroll
    for (int i = 0; i < 5; i++){
        stA[i] = *(const float4*)pA[i];
        stB[i] = *(const float4*)(pA[i] + dBA);
    }
    #pragma unroll
    for (int i = 0; i < 4; i++)
        if (i < 3 || tid < 32) stC[i] = *pC[i];

    for (int c = 0; c < NKC; c++){
        const int b = c & 1;

        // ---- STS staged chunk c into buffer b ----
        #pragma unroll
        for (int i = 0; i < 5; i++){
            int fidx = tid + i*256;
            int row = fidx / 5, col = fidx % 5;
            float* d0 = &Ssm[(size_t)(b*2*KC + 4*col) * SPITCH + row];
            d0[0*SPITCH] = stA[i].x; d0[1*SPITCH] = stA[i].y;
            d0[2*SPITCH] = stA[i].z; d0[3*SPITCH] = stA[i].w;
            float* d1 = d0 + KC*SPITCH;
            d1[0*SPITCH] = stB[i].x; d1[1*SPITCH] = stB[i].y;
            d1[2*SPITCH] = stB[i].z; d1[3*SPITCH] = stB[i].w;
        }
        #pragma unroll
        for (int i = 0; i < 4; i++){
            int cidx = tid + i*256;
            if (cidx < 800) Csm[b*800 + cidx] = stC[i];
        }
        __syncthreads();

        // ---- prefetch chunk c+1 into registers (LDG overlaps compute) ----
        if (c + 1 < NKC){
            #pragma unroll
            for (int i = 0; i < 5; i++){
                pA[i] += KC;
                stA[i] = *(const float4*)pA[i];
                stB[i] = *(const float4*)(pA[i] + dBA);
            }
            #pragma unroll
            for (int i = 0; i < 4; i++){
                pC[i] += KC;
                if (i < 3 || tid < 32) stC[i] = *pC[i];
            }
        }

        // ---- compute chunk c from buffer b ----
        {
            const float* Sp = &Ssm[(size_t)(b*2 + mymat) * KC * SPITCH + 2*m];
            const float* Cp = &Csm[b*800 + n0*KC];
            #pragma unroll
            for (int k = 0; k < KC; k++){
                u64 c2v[5];
                #pragma unroll
                for (int j = 0; j < 5; j++){
                    float cv = Cp[j*KC + k];
                    c2v[j] = pack2(cv, cv);
                }
                u64 s2[4];
                #pragma unroll
                for (int p = 0; p < 4; p++)
                    s2[p] = *(const u64*)&Sp[k*SPITCH + 64*p];
                #pragma unroll
                for (int p = 0; p < 4; p++)
                    #pragma unroll
                    for (int j = 0; j < 5; j++)
                        acc[p][j] = fma2(s2[p], c2v[j], acc[p][j]);
            }
        }
    }

    // ---- epilogue: write row pairs (coalesced float2, [s][t] layout) ----
    #pragma unroll
    for (int p = 0; p < 4; p++){
        int t = row0 + 64*p + 2*m;
        if (t < T_DATA){
            #pragma unroll
            for (int j = 0; j < 5; j++){
                float2 v = unpack2(acc[p][j]);
                *(float2*)&g_syn[mymat][sloc + j][t] = v;
            }
        }
    }
}

// ============================ conv + tree + output ===========================
// out[t] = sum_{d=0..200} wf[d]*x[t-d],  wf[d] = w[200-d]  (causal, zero-padded)
// Then syn_in = conv_e + b_e + conv_i + b_i ;
// Y[t,s] = syn_in[t,s] + sum_s' syn_in[t,s'] * exp(W[s']) * C_den[s,s'] ;
// voltage[t] = Y[t,0]*exp(W[0]).  Outputs: [voltage (T)] [Y (T*20)] [Y (T*20)]
#define CT   256
#define HALO 208
#define XW   464          // CT + HALO
#define WPAD 208          // 201 taps zero-padded to 208 (26 chunks of 8)
#define SINP 264

__global__ __launch_bounds__(256, 1) void conv_kernel(
    const float* __restrict__ w_e, const float* __restrict__ b_e,
    const float* __restrict__ w_i, const float* __restrict__ b_i,
    const float* __restrict__ C_den, const float* __restrict__ Wsub,
    float* __restrict__ out)
{
    extern __shared__ float sm[];
    float* xs   = sm;                        // [2][SUB][XW]
    float* ws   = xs + 2*SUB*XW;             // [2][SUB][WPAD]  flipped + zero pad
    float* sins = ws + 2*SUB*WPAD;           // [SUB][SINP]
    float* Msm  = sins + SUB*SINP;           // [SUB][SUB]  = C_den[s][s'] * exp(W[s'])
    float* expw = Msm + SUB*SUB;             // [SUB]

    const int tid   = threadIdx.x;
    const int tile0 = blockIdx.x * CT;

    // weights (flipped) + padding
    for (int idx = tid; idx < 2*SUB*WPAD; idx += 256){
        int mt = idx / (SUB*WPAD);
        int r  = idx % (SUB*WPAD);
        int s  = r / WPAD, d = r % WPAD;
        const float* w = mt ? w_i : w_e;
        ws[idx] = (d < TSYN) ? w[s*TSYN + (TSYN-1 - d)] : 0.f;
    }
    if (tid < SUB) expw[tid] = expf(Wsub[tid]);
    for (int idx = tid; idx < SUB*SUB; idx += 256){
        int sp = idx % SUB;
        Msm[idx] = C_den[idx] * expf(Wsub[sp]);
    }
    // x tiles (with halo, zero before t=0 / beyond T)
    for (int idx = tid; idx < 2*SUB*(XW/4); idx += 256){
        int mt = idx / (SUB*(XW/4));
        int r  = idx % (SUB*(XW/4));
        int s  = r / (XW/4);
        int j  = (r % (XW/4)) * 4;
        long gt = (long)tile0 - HALO + j;
        float4 v;
        if (gt >= 0 && gt + 3 < (long)T_DATA){
            v = *(const float4*)&g_syn[mt][s][gt];
        } else {
            float tmp[4];
            #pragma unroll
            for (int k2 = 0; k2 < 4; k2++){
                long g2 = gt + k2;
                tmp[k2] = (g2 >= 0 && g2 < (long)T_DATA) ? g_syn[mt][s][g2] : 0.f;
            }
            v = make_float4(tmp[0], tmp[1], tmp[2], tmp[3]);
        }
        *(float4*)&xs[(mt*SUB + s)*XW + j] = v;
    }
    __syncthreads();

    // conv: 5 iterations x 8 warps cover 20 subs x 2 t-halves; lane -> 4 consecutive t
    const int warp = tid >> 5, lane = tid & 31;
    for (int it = 0; it < 5; it++){
        int idx = it*8 + warp;               // 0..39
        int s   = idx % SUB;
        int tch = idx / SUB;
        int t0  = HALO + tch*128 + lane*4;   // local coordinate of first output
        float a0 = 0.f, a1 = 0.f, a2 = 0.f, a3 = 0.f;
        #pragma unroll
        for (int mt = 0; mt < 2; mt++){
            const float* xb = &xs[(mt*SUB + s)*XW];
            const float* wb = &ws[(mt*SUB + s)*WPAD];
            for (int d0 = 0; d0 < WPAD; d0 += 8){     // 26 chunks, reg sliding window
                int wbase = t0 - d0 - 8;              // >= 0, 16B aligned
                float4 qa = *(const float4*)&xb[wbase];
                float4 qb = *(const float4*)&xb[wbase + 4];
                float4 qc = *(const float4*)&xb[wbase + 8];
                float win[12] = {qa.x,qa.y,qa.z,qa.w, qb.x,qb.y,qb.z,qb.w, qc.x,qc.y,qc.z,qc.w};
                #pragma unroll
                for (int dd = 0; dd < 8; dd++){
                    float wv = wb[d0 + dd];           // warp-uniform broadcast
                    a0 += wv * win[ 8 - dd];
                    a1 += wv * win[ 9 - dd];
                    a2 += wv * win[10 - dd];
                    a3 += wv * win[11 - dd];
                }
            }
        }
        float bias = b_e[s] + b_i[s];
        int tl = tch*128 + lane*4;
        float4 o = make_float4(a0 + bias, a1 + bias, a2 + bias, a3 + bias);
        *(float4*)&sins[s*SINP + tl] = o;
    }
    __syncthreads();

    // dendritic one-hop matvec + outputs
    const float ew0 = expw[0];
    float* outV  = out;
    float* outY1 = out + T_DATA;
    float* outY2 = out + T_DATA + (size_t)T_DATA * SUB;
    for (int i = 0; i < 20; i++){
        int idx = i*256 + tid;               // < 5120
        int tl = idx / SUB, s = idx % SUB;
        int t = tile0 + tl;
        if (t < T_DATA){
            float y = sins[s*SINP + tl];
            #pragma unroll
            for (int sp = 0; sp < SUB; sp++)
                y += sins[sp*SINP + tl] * Msm[s*SUB + sp];
            outY1[(size_t)t*SUB + s] = y;
            outY2[(size_t)t*SUB + s] = y;
            if (s == 0) outV[t] = y * ew0;
        }
    }
}

// ================================ launch =====================================
extern "C" void kernel_launch(void* const* d_in, const int* in_sizes, int n_in,
                              void* d_out, int out_size)
{
    const float* S_e   = (const float*)d_in[0];
    const float* S_i   = (const float*)d_in[1];
    const float* C_e   = (const float*)d_in[2];
    const float* C_i   = (const float*)d_in[3];
    const float* C_den = (const float*)d_in[4];
    const float* w_e   = (const float*)d_in[5];
    const float* b_e   = (const float*)d_in[6];
    const float* w_i   = (const float*)d_in[7];
    const float* b_i   = (const float*)d_in[8];
    const float* Wsub  = (const float*)d_in[9];
    float* out = (float*)d_out;

    const size_t gemm_smem = (size_t)(2*2*KC*SPITCH + 2*40*KC) * sizeof(float);          // 88,960 B
    const size_t conv_smem = (size_t)(2*SUB*XW + 2*SUB*WPAD + SUB*SINP + SUB*SUB + SUB)
                             * sizeof(float);                                            // 130,320 B
    cudaFuncSetAttribute(gemm_kernel, cudaFuncAttributeMaxDynamicSharedMemorySize, (int)gemm_smem);
    cudaFuncSetAttribute(conv_kernel, cudaFuncAttributeMaxDynamicSharedMemorySize, (int)conv_smem);

    const int grid = (T_DATA + TM - 1) / TM;   // 391
    gemm_kernel<<<grid, 256, gemm_smem>>>(S_e, S_i, C_e, C_i);
    conv_kernel<<<grid, 256, conv_smem>>>(w_e, b_e, w_i, b_i, C_den, Wsub, out);
}

// round 5
// speedup vs baseline: 1.8738x; 1.8738x over previous
#include <cuda_runtime.h>
#include <math.h>
#include <stdint.h>

#define T_DATA 100000
#define K_DIM  1000
#define SUB    20
#define TSYN   201

// ---------------- device scratch (no allocs allowed) ----------------
__device__ float g_syn[2][SUB][T_DATA];   // GEMM output  [e/i][s][t]
__device__ float g_sin[2][SUB][T_DATA];   // conv output  [e/i][s][t]

// ============================ helpers ========================================
__device__ __forceinline__ uint32_t tf32c(float x){
    uint32_t r; asm("cvt.rna.tf32.f32 %0, %1;" : "=r"(r) : "f"(x)); return r;
}
__device__ __forceinline__ float4 cv4(float4 v){
    float4 o;
    o.x = __uint_as_float(tf32c(v.x));
    o.y = __uint_as_float(tf32c(v.y));
    o.z = __uint_as_float(tf32c(v.z));
    o.w = __uint_as_float(tf32c(v.w));
    return o;
}
__device__ __forceinline__ void mma_t(float4& d,
    uint32_t a0, uint32_t a1, uint32_t a2, uint32_t a3, uint32_t b0, uint32_t b1){
    asm("mma.sync.aligned.m16n8k8.row.col.f32.tf32.tf32.f32 "
        "{%0,%1,%2,%3},{%4,%5,%6,%7},{%8,%9},{%0,%1,%2,%3};"
        : "+f"(d.x), "+f"(d.y), "+f"(d.z), "+f"(d.w)
        : "r"(a0), "r"(a1), "r"(a2), "r"(a3), "r"(b0), "r"(b1));
}

// ============================ GEMM (mma.sync tf32) ===========================
// Per CTA: rows [row0, row0+128). For mat in {e,i}: D[128,24] = A[128,K]*B[24,K]^T
// (B rows 20..23 zero-padded). Smem pitch 36 floats -> conflict-free frags.
#define P36   36
#define AOFS  4608                 // 128*36 floats per A mat
#define BOFS  864                  // 24*36 floats per B mat
#define SF    10944                // stage floats: 2*4608 + 2*864
#define NCHK  32                   // 32 chunks * 32 k = 1024 >= K (zero-pad)

struct StageRegs { float4 ae[8], ai[8], b[3]; };

__global__ __launch_bounds__(128, 2) void mma_gemm(
    const float* __restrict__ Se, const float* __restrict__ Si,
    const float* __restrict__ Ce, const float* __restrict__ Ci)
{
    extern __shared__ float smf[];
    const int tid = threadIdx.x, wid = tid >> 5, lane = tid & 31;
    const int group = lane >> 2, tig = lane & 3;
    const int row0 = blockIdx.x * 128;

    // ---- staging geometry ----
    const int srow = tid >> 3, sc4 = tid & 7;      // A: row = srow+16i, float4-col = sc4
    int aoff[8];
    #pragma unroll
    for (int i = 0; i < 8; i++){
        int r = row0 + srow + 16*i;
        if (r >= T_DATA) r = T_DATA - 1;           // clamp (stores are guarded)
        aoff[i] = r * K_DIM + sc4 * 4;
    }
    const float* bsrc[3]; int boff[3], bsts[3], bc4[3]; bool bvn[3];
    #pragma unroll
    for (int i = 0; i < 3; i++){
        int idx = tid + i*128;                     // < 384
        int mt = (idx >= 192) ? 1 : 0;
        int r  = idx - mt*192;
        int n  = r >> 3, c4 = r & 7;
        bvn[i]  = (n < SUB);
        bc4[i]  = c4;
        int nc  = (n < SUB) ? n : 0;
        bsrc[i] = mt ? Ci : Ce;
        boff[i] = nc * K_DIM + c4 * 4;
        bsts[i] = 2*AOFS + mt*BOFS + n*P36 + c4*4;
    }

    float4 acc[2][2][3];
    #pragma unroll
    for (int mt = 0; mt < 2; mt++)
        #pragma unroll
        for (int m = 0; m < 2; m++)
            #pragma unroll
            for (int nt = 0; nt < 3; nt++)
                acc[mt][m][nt] = make_float4(0.f, 0.f, 0.f, 0.f);

    // ---- stage chunk 0 ----
    StageRegs st;
    {
        const int k0 = 0;
        #pragma unroll
        for (int i = 0; i < 8; i++){
            st.ae[i] = *(const float4*)(Se + aoff[i] + k0);
            st.ai[i] = *(const float4*)(Si + aoff[i] + k0);
        }
        #pragma unroll
        for (int i = 0; i < 3; i++)
            st.b[i] = bvn[i] ? *(const float4*)(bsrc[i] + boff[i] + k0)
                             : make_float4(0.f, 0.f, 0.f, 0.f);
    }

    const int cbaseA = wid*32*P36 + group*P36 + tig;
    const int cbaseB = 2*AOFS + group*P36 + tig;

    for (int c = 0; c < NCHK; c++){
        const int bb = (c & 1) * SF;

        // ---- STS staged chunk c (with tf32 rounding) ----
        #pragma unroll
        for (int i = 0; i < 8; i++){
            int d = bb + (srow + 16*i)*P36 + sc4*4;
            *(float4*)&smf[d]        = cv4(st.ae[i]);
            *(float4*)&smf[d + AOFS] = cv4(st.ai[i]);
        }
        #pragma unroll
        for (int i = 0; i < 3; i++)
            *(float4*)&smf[bb + bsts[i]] = cv4(st.b[i]);
        __syncthreads();

        // ---- prefetch chunk c+1 (LDG overlaps compute) ----
        if (c + 1 < NCHK){
            const int k0 = (c + 1) * 32;
            const bool edge = (c + 1 == NCHK - 1);       // k0 = 992
            #pragma unroll
            for (int i = 0; i < 8; i++){
                bool v = !edge || (sc4 < 2);
                st.ae[i] = v ? *(const float4*)(Se + aoff[i] + k0) : make_float4(0.f,0.f,0.f,0.f);
                st.ai[i] = v ? *(const float4*)(Si + aoff[i] + k0) : make_float4(0.f,0.f,0.f,0.f);
            }
            #pragma unroll
            for (int i = 0; i < 3; i++){
                bool v = bvn[i] && (!edge || (bc4[i] < 2));
                st.b[i] = v ? *(const float4*)(bsrc[i] + boff[i] + k0) : make_float4(0.f,0.f,0.f,0.f);
            }
        }

        // ---- compute chunk c ----
        const float* base = smf + bb;
        #pragma unroll
        for (int ks = 0; ks < 4; ks++){
            const int kb = ks * 8;
            uint32_t A[2][2][4];
            #pragma unroll
            for (int mt = 0; mt < 2; mt++)
                #pragma unroll
                for (int m = 0; m < 2; m++){
                    const float* ab = base + mt*AOFS + cbaseA + m*16*P36 + kb;
                    A[mt][m][0] = __float_as_uint(ab[0]);
                    A[mt][m][1] = __float_as_uint(ab[8*P36]);
                    A[mt][m][2] = __float_as_uint(ab[4]);
                    A[mt][m][3] = __float_as_uint(ab[8*P36 + 4]);
                }
            uint32_t B0[2][3], B1[2][3];
            #pragma unroll
            for (int mt = 0; mt < 2; mt++)
                #pragma unroll
                for (int nt = 0; nt < 3; nt++){
                    const float* bbp = base + mt*BOFS + cbaseB + nt*8*P36 + kb;
                    B0[mt][nt] = __float_as_uint(bbp[0]);
                    B1[mt][nt] = __float_as_uint(bbp[4]);
                }
            #pragma unroll
            for (int mt = 0; mt < 2; mt++)
                #pragma unroll
                for (int m = 0; m < 2; m++)
                    #pragma unroll
                    for (int nt = 0; nt < 3; nt++)
                        mma_t(acc[mt][m][nt],
                              A[mt][m][0], A[mt][m][1], A[mt][m][2], A[mt][m][3],
                              B0[mt][nt], B1[mt][nt]);
        }
    }

    // ---- epilogue: D frag -> g_syn[mt][n][t] ----
    #pragma unroll
    for (int mt = 0; mt < 2; mt++)
        #pragma unroll
        for (int m = 0; m < 2; m++)
            #pragma unroll
            for (int nt = 0; nt < 3; nt++){
                float4 d = acc[mt][m][nt];
                int t0 = row0 + wid*32 + m*16 + group;
                int n0 = nt*8 + tig*2;
                if (n0 < SUB){
                    if (t0 < T_DATA){
                        g_syn[mt][n0][t0]     = d.x;
                        g_syn[mt][n0 + 1][t0] = d.y;
                    }
                    if (t0 + 8 < T_DATA){
                        g_syn[mt][n0][t0 + 8]     = d.z;
                        g_syn[mt][n0 + 1][t0 + 8] = d.w;
                    }
                }
            }
}

// ============================ depthwise conv =================================
// out[t] = sum_{k=0..200} w[k] * x[t-200+k]  (front zero-pad; straight correlation)
#define TT 2048

__global__ __launch_bounds__(256) void conv_kernel(
    const float* __restrict__ w_e, const float* __restrict__ w_i)
{
    __shared__ __align__(16) float xs[TT + 232];
    __shared__ __align__(16) float ws[204];

    const int tid = threadIdx.x;
    const long tile0 = (long)blockIdx.x * TT;
    const int id = blockIdx.y;                 // 0..39
    const int mt = id / SUB, s = id % SUB;
    const float* xg = g_syn[mt][s];

    // xs[j] = x(tile0 - 208 + j)    (208 keeps 16-B global alignment)
    for (int idx = tid; idx < (TT + 232)/4; idx += 256){
        long gt = tile0 - 208 + (long)idx*4;
        float4 v;
        if (gt >= 0 && gt + 3 < T_DATA){
            v = *(const float4*)&xg[gt];
        } else {
            float tmp[4];
            #pragma unroll
            for (int k2 = 0; k2 < 4; k2++){
                long g2 = gt + k2;
                tmp[k2] = (g2 >= 0 && g2 < T_DATA) ? xg[g2] : 0.f;
            }
            v = make_float4(tmp[0], tmp[1], tmp[2], tmp[3]);
        }
        *(float4*)&xs[idx*4] = v;
    }
    const float* w = mt ? w_i : w_e;
    for (int idx = tid; idx < 204; idx += 256)
        ws[idx] = (idx < TSYN) ? w[s*TSYN + idx] : 0.f;
    __syncthreads();

    const int tl0 = tid * 8;
    const int x0  = tl0 + 8;                 // xs index of tap k=0 for output tl0
    float a[8];
    #pragma unroll
    for (int j = 0; j < 8; j++) a[j] = 0.f;

    float r[12];
    #pragma unroll
    for (int j = 0; j < 12; j += 4)
        *(float4*)&r[j] = *(const float4*)&xs[x0 + j];

    #pragma unroll
    for (int kb = 0; kb < 204; kb += 4){
        float4 w4 = *(const float4*)&ws[kb];
        #pragma unroll
        for (int j = 0; j < 8; j++)
            a[j] += w4.x*r[j] + w4.y*r[j+1] + w4.z*r[j+2] + w4.w*r[j+3];
        if (kb < 200){
            #pragma unroll
            for (int j = 0; j < 8; j++) r[j] = r[j+4];
            *(float4*)&r[8] = *(const float4*)&xs[x0 + kb + 12];
        }
    }

    long tb = tile0 + tl0;
    if (tb + 7 < T_DATA){
        *(float4*)&g_sin[mt][s][tb]     = make_float4(a[0], a[1], a[2], a[3]);
        *(float4*)&g_sin[mt][s][tb + 4] = make_float4(a[4], a[5], a[6], a[7]);
    } else {
        #pragma unroll
        for (int j = 0; j < 8; j++)
            if (tb + j < T_DATA) g_sin[mt][s][tb + j] = a[j];
    }
}

// ============================ dendritic mix + outputs ========================
__global__ __launch_bounds__(256) void mix_kernel(
    const float* __restrict__ C_den, const float* __restrict__ b_e,
    const float* __restrict__ b_i,   const float* __restrict__ Wsub,
    float* __restrict__ out)
{
    __shared__ float si[SUB][260];
    __shared__ float M[SUB][SUB];
    __shared__ float ew0s;

    const int tid = threadIdx.x;
    const long tile0 = (long)blockIdx.x * 256;

    for (int idx = tid; idx < SUB*SUB; idx += 256){
        int sp = idx % SUB;
        M[idx / SUB][sp] = C_den[idx] * expf(Wsub[sp]);
    }
    if (tid == 0) ew0s = expf(Wsub[0]);

    const long t = tile0 + tid;
    #pragma unroll
    for (int sx = 0; sx < SUB; sx++){
        float v = 0.f;
        if (t < T_DATA)
            v = g_sin[0][sx][t] + g_sin[1][sx][t] + b_e[sx] + b_i[sx];
        si[sx][tid] = v;
    }
    __syncthreads();

    float* outV  = out;
    float* outY1 = out + T_DATA;
    float* outY2 = outY1 + (size_t)T_DATA * SUB;
    const float ew0 = ew0s;

    for (int i = 0; i < 20; i++){
        int idx = i*256 + tid;               // < 5120
        int tl = idx / SUB, sx = idx % SUB;
        long tt = tile0 + tl;
        if (tt < T_DATA){
            float y = si[sx][tl];
            #pragma unroll
            for (int sp = 0; sp < SUB; sp++)
                y += si[sp][tl] * M[sx][sp];
            outY1[tt*SUB + sx] = y;
            outY2[tt*SUB + sx] = y;
            if (sx == 0) outV[tt] = y * ew0;
        }
    }
}

// ================================ launch =====================================
extern "C" void kernel_launch(void* const* d_in, const int* in_sizes, int n_in,
                              void* d_out, int out_size)
{
    const float* S_e   = (const float*)d_in[0];
    const float* S_i   = (const float*)d_in[1];
    const float* C_e   = (const float*)d_in[2];
    const float* C_i   = (const float*)d_in[3];
    const float* C_den = (const float*)d_in[4];
    const float* w_e   = (const float*)d_in[5];
    const float* b_e   = (const float*)d_in[6];
    const float* w_i   = (const float*)d_in[7];
    const float* b_i   = (const float*)d_in[8];
    const float* Wsub  = (const float*)d_in[9];
    float* out = (float*)d_out;

    const int gemm_smem = 2 * SF * sizeof(float);   // 87,552 B -> 2 CTAs/SM
    cudaFuncSetAttribute(mma_gemm, cudaFuncAttributeMaxDynamicSharedMemorySize, gemm_smem);

    const int grid = (T_DATA + 127) / 128;          // 782
    mma_gemm<<<grid, 128, gemm_smem>>>(S_e, S_i, C_e, C_i);
    conv_kernel<<<dim3((T_DATA + TT - 1)/TT, 40), 256>>>(w_e, w_i);
    mix_kernel<<<(T_DATA + 255)/256, 256>>>(C_den, b_e, b_i, Wsub, out);
}

// round 7
// speedup vs baseline: 2.2226x; 1.1862x over previous
#include <cuda_runtime.h>
#include <math.h>
#include <stdint.h>

#define T_DATA 100000
#define K_DIM  1000
#define SUB    20
#define TSYN   201

// ---------------- device scratch (no allocs allowed) ----------------
__device__ float g_syn[2][SUB][T_DATA];   // GEMM output  [e/i][s][t]
__device__ float g_sin[2][SUB][T_DATA];   // conv output  [e/i][s][t]

// ============================ helpers ========================================
__device__ __forceinline__ uint32_t smem_u32(const void* p){
    uint32_t a;
    asm("{ .reg .u64 t; cvta.to.shared.u64 t, %1; cvt.u32.u64 %0, t; }" : "=r"(a) : "l"(p));
    return a;
}
__device__ __forceinline__ uint32_t tf32c(float x){
    uint32_t r; asm("cvt.rna.tf32.f32 %0, %1;" : "=r"(r) : "f"(x)); return r;
}
__device__ __forceinline__ void mma_t(float4& d,
    uint32_t a0, uint32_t a1, uint32_t a2, uint32_t a3, uint32_t b0, uint32_t b1){
    asm("mma.sync.aligned.m16n8k8.row.col.f32.tf32.tf32.f32 "
        "{%0,%1,%2,%3},{%4,%5,%6,%7},{%8,%9},{%0,%1,%2,%3};"
        : "+f"(d.x), "+f"(d.y), "+f"(d.z), "+f"(d.w)
        : "r"(a0), "r"(a1), "r"(a2), "r"(a3), "r"(b0), "r"(b1));
}
__device__ __forceinline__ void cpa16(uint32_t dst, const float* src, uint32_t szb){
    asm volatile("cp.async.cg.shared.global [%0], [%1], 16, %2;"
                 :: "r"(dst), "l"(src), "r"(szb) : "memory");
}
#define CP_COMMIT() asm volatile("cp.async.commit_group;" ::: "memory")
#define CP_WAIT(n)  asm volatile("cp.async.wait_group %0;" :: "n"(n) : "memory")

// ============================ GEMM (mma.sync tf32, cp.async pipeline) ========
// Per CTA: rows [row0, row0+128). For mat in {e,i}: D[128,24] = A[128,K]*B[24,K]^T
// (B rows 20..23 zero-filled). Pitch 20 floats -> conflict-free frags.
#define PCH    20
#define A_OFS  2560                // 128*20 floats per A mat
#define B_OFS  480                 // 24*20 floats per B mat
#define STGF   6080                // floats/stage: 2*2560 + 2*480 (24320 B)
#define NSTG   3
#define NCHK   63                  // 63 chunks * 16 k = 1008 >= K (zero-fill)

__global__ __launch_bounds__(128, 3) void mma_gemm(
    const float* __restrict__ Se, const float* __restrict__ Si,
    const float* __restrict__ Ce, const float* __restrict__ Ci)
{
    extern __shared__ float smf[];
    const uint32_t smb = smem_u32(smf);
    const int tid = threadIdx.x, wid = tid >> 5, lane = tid & 31;
    const int group = lane >> 2, tig = lane & 3;
    const int row0 = blockIdx.x * 128;

    // ---- cp.async staging geometry ----
    // A: idx = i*128 + tid, i<8 : mt = i>>2, row = (tid>>2) + (i&3)*32, c4 = tid&3
    const int ac4 = tid & 3;
    const float* aG[8]; uint32_t aS[8];
    #pragma unroll
    for (int i = 0; i < 8; i++){
        int mt  = i >> 2;
        int row = (tid >> 2) + (i & 3) * 32;
        int gr  = row0 + row; if (gr >= T_DATA) gr = T_DATA - 1;   // clamp (stores guarded)
        aG[i] = (mt ? Si : Se) + (size_t)gr * K_DIM + ac4 * 4;
        aS[i] = (uint32_t)(mt * A_OFS + row * PCH + ac4 * 4) * 4u;
    }
    // B: slots idx = tid, tid+128 ; valid idx < 192 ; mt=idx/96, r=idx%96, n=r/4, c4=r%4
    const float* bG[2]; uint32_t bS[2]; int bc4[2]; bool bslot[2], bval[2];
    #pragma unroll
    for (int i = 0; i < 2; i++){
        int idx = tid + i * 128;
        bslot[i] = (idx < 192);
        int id2 = bslot[i] ? idx : 0;
        int mt = id2 / 96, r = id2 % 96, n = r >> 2, c4 = r & 3;
        bc4[i]  = c4;
        bval[i] = (n < SUB);
        int nc  = (n < SUB) ? n : 0;
        bG[i] = (mt ? Ci : Ce) + (size_t)nc * K_DIM + c4 * 4;
        bS[i] = (uint32_t)(2 * A_OFS + mt * B_OFS + n * PCH + c4 * 4) * 4u;
    }

    float4 acc[2][2][3];
    #pragma unroll
    for (int mt = 0; mt < 2; mt++)
        #pragma unroll
        for (int m = 0; m < 2; m++)
            #pragma unroll
            for (int nt = 0; nt < 3; nt++)
                acc[mt][m][nt] = make_float4(0.f, 0.f, 0.f, 0.f);

    // ---- issue one chunk's cp.async group ----
    auto issue = [&](int c){
        const uint32_t sbase = smb + (uint32_t)(c % NSTG) * (STGF * 4u);
        const int k0 = c * 16;
        const uint32_t szA = (k0 + ac4 * 4 < K_DIM) ? 16u : 0u;
        #pragma unroll
        for (int i = 0; i < 8; i++)
            cpa16(sbase + aS[i], aG[i] + k0, szA);
        #pragma unroll
        for (int i = 0; i < 2; i++)
            if (bslot[i]){
                uint32_t sz = (bval[i] && (k0 + bc4[i] * 4 < K_DIM)) ? 16u : 0u;
                cpa16(sbase + bS[i], bG[i] + k0, sz);
            }
        CP_COMMIT();
    };

    issue(0);
    issue(1);

    const int cbaseA = wid * 32 * PCH + group * PCH + tig;
    const int cbaseB = 2 * A_OFS + group * PCH + tig;

    for (int c = 0; c < NCHK; c++){
        if (c < NCHK - 1) { CP_WAIT(1); } else { CP_WAIT(0); }
        __syncthreads();
        if (c + 2 < NCHK) issue(c + 2);

        const float* base = smf + (c % NSTG) * STGF;
        #pragma unroll
        for (int ks = 0; ks < 2; ks++){
            const int kb = ks * 8;
            uint32_t A[2][2][4];
            #pragma unroll
            for (int mt = 0; mt < 2; mt++)
                #pragma unroll
                for (int m = 0; m < 2; m++){
                    const float* ab = base + mt * A_OFS + cbaseA + m * 16 * PCH + kb;
                    A[mt][m][0] = tf32c(ab[0]);
                    A[mt][m][1] = tf32c(ab[8 * PCH]);
                    A[mt][m][2] = tf32c(ab[4]);
                    A[mt][m][3] = tf32c(ab[8 * PCH + 4]);
                }
            uint32_t B0[2][3], B1[2][3];
            #pragma unroll
            for (int mt = 0; mt < 2; mt++)
                #pragma unroll
                for (int nt = 0; nt < 3; nt++){
                    const float* bbp = base + mt * B_OFS + cbaseB + nt * 8 * PCH + kb;
                    B0[mt][nt] = tf32c(bbp[0]);
                    B1[mt][nt] = tf32c(bbp[4]);
                }
            #pragma unroll
            for (int mt = 0; mt < 2; mt++)
                #pragma unroll
                for (int m = 0; m < 2; m++)
                    #pragma unroll
                    for (int nt = 0; nt < 3; nt++)
                        mma_t(acc[mt][m][nt],
                              A[mt][m][0], A[mt][m][1], A[mt][m][2], A[mt][m][3],
                              B0[mt][nt], B1[mt][nt]);
        }
    }

    // ---- epilogue: D frag -> g_syn[mt][n][t] ----
    #pragma unroll
    for (int mt = 0; mt < 2; mt++)
        #pragma unroll
        for (int m = 0; m < 2; m++)
            #pragma unroll
            for (int nt = 0; nt < 3; nt++){
                float4 d = acc[mt][m][nt];
                int t0 = row0 + wid * 32 + m * 16 + group;
                int n0 = nt * 8 + tig * 2;
                if (n0 < SUB){
                    if (t0 < T_DATA){
                        g_syn[mt][n0][t0]     = d.x;
                        g_syn[mt][n0 + 1][t0] = d.y;
                    }
                    if (t0 + 8 < T_DATA){
                        g_syn[mt][n0][t0 + 8]     = d.z;
                        g_syn[mt][n0 + 1][t0 + 8] = d.w;
                    }
                }
            }
}

// ============================ depthwise conv =================================
// out[t] = sum_{k=0..200} w[k] * x[t-200+k]  (front zero-pad; straight correlation)
#define TT 2048

__global__ __launch_bounds__(256) void conv_kernel(
    const float* __restrict__ w_e, const float* __restrict__ w_i)
{
    __shared__ __align__(16) float xs[TT + 232];
    __shared__ __align__(16) float ws[204];

    const int tid = threadIdx.x;
    const long tile0 = (long)blockIdx.x * TT;
    const int id = blockIdx.y;                 // 0..39
    const int mt = id / SUB, s = id % SUB;
    const float* xg = g_syn[mt][s];

    // xs[j] = x(tile0 - 208 + j)    (208 keeps 16-B global alignment)
    for (int idx = tid; idx < (TT + 232)/4; idx += 256){
        long gt = tile0 - 208 + (long)idx*4;
        float4 v;
        if (gt >= 0 && gt + 3 < T_DATA){
            v = *(const float4*)&xg[gt];
        } else {
            float tmp[4];
            #pragma unroll
            for (int k2 = 0; k2 < 4; k2++){
                long g2 = gt + k2;
                tmp[k2] = (g2 >= 0 && g2 < T_DATA) ? xg[g2] : 0.f;
            }
            v = make_float4(tmp[0], tmp[1], tmp[2], tmp[3]);
        }
        *(float4*)&xs[idx*4] = v;
    }
    const float* w = mt ? w_i : w_e;
    for (int idx = tid; idx < 204; idx += 256)
        ws[idx] = (idx < TSYN) ? w[s*TSYN + idx] : 0.f;
    __syncthreads();

    const int tl0 = tid * 8;
    const int x0  = tl0 + 8;                 // xs index of tap k=0 for output tl0
    float a[8];
    #pragma unroll
    for (int j = 0; j < 8; j++) a[j] = 0.f;

    float r[12];
    #pragma unroll
    for (int j = 0; j < 12; j += 4)
        *(float4*)&r[j] = *(const float4*)&xs[x0 + j];

    #pragma unroll
    for (int kb = 0; kb < 204; kb += 4){
        float4 w4 = *(const float4*)&ws[kb];
        #pragma unroll
        for (int j = 0; j < 8; j++)
            a[j] += w4.x*r[j] + w4.y*r[j+1] + w4.z*r[j+2] + w4.w*r[j+3];
        if (kb < 200){
            #pragma unroll
            for (int j = 0; j < 8; j++) r[j] = r[j+4];
            *(float4*)&r[8] = *(const float4*)&xs[x0 + kb + 12];
        }
    }

    long tb = tile0 + tl0;
    if (tb + 7 < T_DATA){
        *(float4*)&g_sin[mt][s][tb]     = make_float4(a[0], a[1], a[2], a[3]);
        *(float4*)&g_sin[mt][s][tb + 4] = make_float4(a[4], a[5], a[6], a[7]);
    } else {
        #pragma unroll
        for (int j = 0; j < 8; j++)
            if (tb + j < T_DATA) g_sin[mt][s][tb + j] = a[j];
    }
}

// ============================ dendritic mix + outputs ========================
__global__ __launch_bounds__(256) void mix_kernel(
    const float* __restrict__ C_den, const float* __restrict__ b_e,
    const float* __restrict__ b_i,   const float* __restrict__ Wsub,
    float* __restrict__ out)
{
    __shared__ float si[SUB][260];
    __shared__ float M[SUB][SUB];
    __shared__ float ew0s;

    const int tid = threadIdx.x;
    const long tile0 = (long)blockIdx.x * 256;

    for (int idx = tid; idx < SUB*SUB; idx += 256){
        int sp = idx % SUB;
        M[idx / SUB][sp] = C_den[idx] * expf(Wsub[sp]);
    }
    if (tid == 0) ew0s = expf(Wsub[0]);

    const long t = tile0 + tid;
    #pragma unroll
    for (int sx = 0; sx < SUB; sx++){
        float v = 0.f;
        if (t < T_DATA)
            v = g_sin[0][sx][t] + g_sin[1][sx][t] + b_e[sx] + b_i[sx];
        si[sx][tid] = v;
    }
    __syncthreads();

    float* outV  = out;
    float* outY1 = out + T_DATA;
    float* outY2 = outY1 + (size_t)T_DATA * SUB;
    const float ew0 = ew0s;

    for (int i = 0; i < 20; i++){
        int idx = i*256 + tid;               // < 5120
        int tl = idx / SUB, sx = idx % SUB;
        long tt = tile0 + tl;
        if (tt < T_DATA){
            float y = si[sx][tl];
            #pragma unroll
            for (int sp = 0; sp < SUB; sp++)
                y += si[sp][tl] * M[sx][sp];
            outY1[tt*SUB + sx] = y;
            outY2[tt*SUB + sx] = y;
            if (sx == 0) outV[tt] = y * ew0;
        }
    }
}

// ================================ launch =====================================
extern "C" void kernel_launch(void* const* d_in, const int* in_sizes, int n_in,
                              void* d_out, int out_size)
{
    const float* S_e   = (const float*)d_in[0];
    const float* S_i   = (const float*)d_in[1];
    const float* C_e   = (const float*)d_in[2];
    const float* C_i   = (const float*)d_in[3];
    const float* C_den = (const float*)d_in[4];
    const float* w_e   = (const float*)d_in[5];
    const float* b_e   = (const float*)d_in[6];
    const float* w_i   = (const float*)d_in[7];
    const float* b_i   = (const float*)d_in[8];
    const float* Wsub  = (const float*)d_in[9];
    float* out = (float*)d_out;

    const int gemm_smem = NSTG * STGF * sizeof(float);   // 72,960 B -> 3 CTAs/SM
    cudaFuncSetAttribute(mma_gemm, cudaFuncAttributeMaxDynamicSharedMemorySize, gemm_smem);

    const int grid = (T_DATA + 127) / 128;               // 782
    mma_gemm<<<grid, 128, gemm_smem>>>(S_e, S_i, C_e, C_i);
    conv_kernel<<<dim3((T_DATA + TT - 1)/TT, 40), 256>>>(w_e, w_i);
    mix_kernel<<<(T_DATA + 255)/256, 256>>>(C_den, b_e, b_i, Wsub, out);
}